// round 10
// baseline (speedup 1.0000x reference)
#include <cuda_runtime.h>
#include <cuda_fp16.h>
#include <cstdint>

#define N_NODES 100000
#define E_EDGES 1600000
#define IN_CH   128
#define HEADS   4
#define OUT_CH  32
#define OC      (HEADS * OUT_CH)   // 128
#define NEG_SLOPE 0.2f

#define SCAN_BLK 1024
#define N_SCAN_BLOCKS ((N_NODES + SCAN_BLK - 1) / SCAN_BLK)   // 98
#define GEMM_CTAS ((N_NODES + 127) / 128)                     // 782
#define EDGES_PER_CTA ((E_EDGES + GEMM_CTAS - 1) / GEMM_CTAS) // 2047

// ---------------- scratch (device globals; no allocation allowed) ----------
__device__ __align__(16) __half g_hh[(size_t)GEMM_CTAS * 128 * OC]; // fp16 h (padded)
__device__ __align__(16) float  g_ssrc[N_NODES * HEADS];
__device__ __align__(16) float  g_sdst[N_NODES * HEADS];
__device__ int g_csr_src[E_EDGES];
__device__ int g_deg[N_NODES];
__device__ int g_off[N_NODES + 1];
__device__ int g_cursor[N_NODES];
__device__ int g_bsum[N_SCAN_BLOCKS];
__device__ int g_bpre[N_SCAN_BLOCKS];
__device__ unsigned g_maxss[HEADS];
__device__ int g_is64;

__device__ __forceinline__ unsigned fenc(float f) {
    unsigned u = __float_as_uint(f);
    return (u & 0x80000000u) ? ~u : (u | 0x80000000u);
}
__device__ __forceinline__ float fdec(unsigned u) {
    return (u & 0x80000000u) ? __uint_as_float(u ^ 0x80000000u)
                             : __uint_as_float(~u);
}
__device__ __forceinline__ float leaky(float v) {
    return (v >= 0.f) ? v : NEG_SLOPE * v;
}

__device__ __forceinline__ void mma16816(float& d0, float& d1, float& d2, float& d3,
                                         unsigned a0, unsigned a1, unsigned a2, unsigned a3,
                                         unsigned b0, unsigned b1) {
    asm volatile("mma.sync.aligned.m16n8k16.row.col.f32.f16.f16.f32 "
                 "{%0,%1,%2,%3}, {%4,%5,%6,%7}, {%8,%9}, {%0,%1,%2,%3};"
                 : "+f"(d0), "+f"(d1), "+f"(d2), "+f"(d3)
                 : "r"(a0), "r"(a1), "r"(a2), "r"(a3), "r"(b0), "r"(b1));
}

// ---------------- K0: init + parallel dtype detect ---------------------------
__global__ void k_init(const unsigned* __restrict__ ei32) {
    const int i = blockIdx.x * blockDim.x + threadIdx.x;
    if (i < N_NODES) g_deg[i] = 0;
    if (i < HEADS) g_maxss[i] = fenc(-__int_as_float(0x7f800000));
    if (blockIdx.x == 0 && threadIdx.x < 64) {
        const unsigned w = ei32[2 * threadIdx.x + 1];
        const unsigned nz = __ballot_sync(0xffffffffu, w != 0u);  // per half-warp group
        // combine across the two warps via shared flag
        __shared__ int anynz;
        if (threadIdx.x == 0) anynz = 0;
        __syncthreads();
        if (nz) atomicOr(&anynz, 1);
        __syncthreads();
        if (threadIdx.x == 0) g_is64 = anynz ? 0 : 1;
    }
}

// ---------------- K1: tensor-core GEMM + fused scores + fused histogram ----
#define APAD 72   // 64 + 8 halves pad
__global__ void __launch_bounds__(256) k_gemm_mma(const float* __restrict__ x,
                                                  const float* __restrict__ W,
                                                  const float* __restrict__ att,
                                                  const void* __restrict__ ei) {
    __shared__ __half As[128][APAD];
    __shared__ __half Bs[128][APAD];

    const int nbase = blockIdx.x * 128;
    const int t = threadIdx.x;
    const int wid = t >> 5;
    const int lane = t & 31;
    const int g = lane >> 2;
    const int tid = lane & 3;

    float d[16][4];
    #pragma unroll
    for (int nt = 0; nt < 16; nt++)
        #pragma unroll
        for (int q = 0; q < 4; q++) d[nt][q] = 0.f;

    #pragma unroll
    for (int kp = 0; kp < 2; kp++) {
        #pragma unroll
        for (int i = 0; i < 8; i++) {
            const int id = t + i * 256;
            const int row = id >> 4;
            const int c4 = (id & 15) * 4;
            const int node = nbase + row;
            float4 v = make_float4(0.f, 0.f, 0.f, 0.f);
            if (node < N_NODES)
                v = __ldg((const float4*)(x + (size_t)node * IN_CH + kp * 64 + c4));
            __half h4[4] = {__float2half_rn(v.x), __float2half_rn(v.y),
                            __float2half_rn(v.z), __float2half_rn(v.w)};
            *(uint2*)&As[row][c4] = *(uint2*)h4;
        }
        #pragma unroll
        for (int i = 0; i < 8; i++) {
            const int id = t + i * 256;
            const int k = id >> 5;
            const int n4 = (id & 31) * 4;
            const float4 w4 = __ldg((const float4*)(W + (size_t)(kp * 64 + k) * OC + n4));
            Bs[n4 + 0][k] = __float2half_rn(w4.x);
            Bs[n4 + 1][k] = __float2half_rn(w4.y);
            Bs[n4 + 2][k] = __float2half_rn(w4.z);
            Bs[n4 + 3][k] = __float2half_rn(w4.w);
        }
        __syncthreads();

        const int r0 = wid * 16 + g;
        #pragma unroll
        for (int ks = 0; ks < 4; ks++) {
            const int kk = ks * 16 + tid * 2;
            const unsigned a0 = *(const unsigned*)&As[r0][kk];
            const unsigned a1 = *(const unsigned*)&As[r0 + 8][kk];
            const unsigned a2 = *(const unsigned*)&As[r0][kk + 8];
            const unsigned a3 = *(const unsigned*)&As[r0 + 8][kk + 8];
            #pragma unroll
            for (int nt = 0; nt < 16; nt++) {
                const int n = nt * 8 + g;
                const unsigned b0 = *(const unsigned*)&Bs[n][kk];
                const unsigned b1 = *(const unsigned*)&Bs[n][kk + 8];
                mma16816(d[nt][0], d[nt][1], d[nt][2], d[nt][3],
                         a0, a1, a2, a3, b0, b1);
            }
        }
        __syncthreads();
    }

    // ---- epilogue: store h (fp16) + fused scores ----
    const int node0 = nbase + wid * 16 + g;
    const int node1 = node0 + 8;

    #pragma unroll
    for (int nt = 0; nt < 16; nt++) {
        const int col = nt * 8 + tid * 2;
        const __half2 h01 = __floats2half2_rn(d[nt][0], d[nt][1]);
        const __half2 h23 = __floats2half2_rn(d[nt][2], d[nt][3]);
        *(__half2*)(g_hh + (size_t)node0 * OC + col) = h01;
        *(__half2*)(g_hh + (size_t)node1 * OC + col) = h23;
    }

    float ssA[4] = {0,0,0,0}, sdA[4] = {0,0,0,0};
    float ssB[4] = {0,0,0,0}, sdB[4] = {0,0,0,0};
    #pragma unroll
    for (int h = 0; h < 4; h++) {
        #pragma unroll
        for (int j = 0; j < 4; j++) {
            const int nt = h * 4 + j;
            const int off = j * 8 + tid * 2;
            const float2 as2 = __ldg((const float2*)(att + h * 64 + off));
            const float2 ad2 = __ldg((const float2*)(att + h * 64 + 32 + off));
            ssA[h] += d[nt][0] * as2.x + d[nt][1] * as2.y;
            sdA[h] += d[nt][0] * ad2.x + d[nt][1] * ad2.y;
            ssB[h] += d[nt][2] * as2.x + d[nt][3] * as2.y;
            sdB[h] += d[nt][2] * ad2.x + d[nt][3] * ad2.y;
        }
    }
    #pragma unroll
    for (int h = 0; h < 4; h++) {
        #pragma unroll
        for (int off = 1; off <= 2; off <<= 1) {
            ssA[h] += __shfl_xor_sync(0xffffffffu, ssA[h], off);
            sdA[h] += __shfl_xor_sync(0xffffffffu, sdA[h], off);
            ssB[h] += __shfl_xor_sync(0xffffffffu, ssB[h], off);
            sdB[h] += __shfl_xor_sync(0xffffffffu, sdB[h], off);
        }
    }
    if (tid == 0) {
        if (node0 < N_NODES) {
            *(float4*)(g_ssrc + (size_t)node0 * 4) = make_float4(ssA[0], ssA[1], ssA[2], ssA[3]);
            *(float4*)(g_sdst + (size_t)node0 * 4) = make_float4(sdA[0], sdA[1], sdA[2], sdA[3]);
        }
        if (node1 < N_NODES) {
            *(float4*)(g_ssrc + (size_t)node1 * 4) = make_float4(ssB[0], ssB[1], ssB[2], ssB[3]);
            *(float4*)(g_sdst + (size_t)node1 * 4) = make_float4(sdB[0], sdB[1], sdB[2], sdB[3]);
        }
    }
    const float NINF = -__int_as_float(0x7f800000);
    float mm[4];
    #pragma unroll
    for (int h = 0; h < 4; h++) {
        float a = (node0 < N_NODES) ? ssA[h] : NINF;
        float b = (node1 < N_NODES) ? ssB[h] : NINF;
        mm[h] = fmaxf(a, b);
        #pragma unroll
        for (int off = 4; off <= 16; off <<= 1)
            mm[h] = fmaxf(mm[h], __shfl_xor_sync(0xffffffffu, mm[h], off));
    }
    if (lane < 4)
        atomicMax(&g_maxss[lane], fenc(mm[lane]));

    // ---- fused degree histogram over this CTA's edge slice ----
    const int ebase = blockIdx.x * EDGES_PER_CTA;
    const int is64 = g_is64;
    #pragma unroll 4
    for (int i = t; i < EDGES_PER_CTA; i += 256) {
        const int e = ebase + i;
        if (e < E_EDGES) {
            int dst;
            if (is64) dst = (int)((const long long*)ei)[E_EDGES + e];
            else      dst = ((const int*)ei)[E_EDGES + e];
            atomicAdd(&g_deg[dst], 1);
        }
    }
}

// ---------------- K3a/b/c: device-wide exclusive scan ------------------------
__global__ void __launch_bounds__(SCAN_BLK) k_scan_local() {
    __shared__ int ws[32];
    const int t = threadIdx.x;
    const int lane = t & 31;
    const int warp = t >> 5;
    const int i = blockIdx.x * SCAN_BLK + t;

    const int val = (i < N_NODES) ? g_deg[i] : 0;
    int v = val;
    #pragma unroll
    for (int d = 1; d < 32; d <<= 1) {
        const int u = __shfl_up_sync(0xffffffffu, v, d);
        if (lane >= d) v += u;
    }
    if (lane == 31) ws[warp] = v;
    __syncthreads();
    if (warp == 0) {
        int w = ws[lane];
        #pragma unroll
        for (int d = 1; d < 32; d <<= 1) {
            const int u = __shfl_up_sync(0xffffffffu, w, d);
            if (lane >= d) w += u;
        }
        ws[lane] = w;
    }
    __syncthreads();
    const int incl = v + (warp ? ws[warp - 1] : 0);
    if (i < N_NODES) g_off[i] = incl - val;
    if (t == SCAN_BLK - 1) g_bsum[blockIdx.x] = incl;
}

__global__ void __launch_bounds__(128) k_scan_bsum() {
    __shared__ int ws[4];
    const int t = threadIdx.x;
    const int lane = t & 31;
    const int warp = t >> 5;
    const int val = (t < N_SCAN_BLOCKS) ? g_bsum[t] : 0;
    int v = val;
    #pragma unroll
    for (int d = 1; d < 32; d <<= 1) {
        const int u = __shfl_up_sync(0xffffffffu, v, d);
        if (lane >= d) v += u;
    }
    if (lane == 31) ws[warp] = v;
    __syncthreads();
    int wpre = 0;
    #pragma unroll
    for (int w = 0; w < 4; w++) if (w < warp) wpre += ws[w];
    if (t < N_SCAN_BLOCKS) g_bpre[t] = v - val + wpre;
}

__global__ void __launch_bounds__(SCAN_BLK) k_scan_final() {
    const int i = blockIdx.x * SCAN_BLK + threadIdx.x;
    if (i < N_NODES) {
        const int o = g_off[i] + g_bpre[blockIdx.x];
        g_off[i] = o;
        g_cursor[i] = o;
    }
    if (i == 0) g_off[N_NODES] = E_EDGES;
}

// ---------------- K4: CSR position scatter, 2 edges/thread ------------------
__global__ void k_edge2(const void* __restrict__ ei) {
    const int e = (blockIdx.x * blockDim.x + threadIdx.x) * 2;
    if (e >= E_EDGES) return;
    int s0, s1, d0, d1;
    if (g_is64) {
        const uint4 sv = *(const uint4*)((const long long*)ei + e);
        const uint4 dv = *(const uint4*)((const long long*)ei + E_EDGES + e);
        s0 = (int)sv.x; s1 = (int)sv.z;
        d0 = (int)dv.x; d1 = (int)dv.z;
    } else {
        const int2 sv = *(const int2*)((const int*)ei + e);
        const int2 dv = *(const int2*)((const int*)ei + E_EDGES + e);
        s0 = sv.x; s1 = sv.y;
        d0 = dv.x; d1 = dv.y;
    }
    const int p0 = atomicAdd(&g_cursor[d0], 1);
    const int p1 = atomicAdd(&g_cursor[d1], 1);
    g_csr_src[p0] = s0;
    g_csr_src[p1] = s1;
}

// ---------------- K5: aggregation w/ on-the-fly softmax (1 warp/node) ------
__device__ __forceinline__ void edge_fma(int src, float sd, float bnd, int head, int c0,
                                         float4& acc, float& sumw) {
    const float ss = __ldg(g_ssrc + (size_t)src * 4 + head);
    const float w = __expf(leaky(ss + sd) - bnd);
    const uint2 r = *(const uint2*)(g_hh + (size_t)src * OC + c0);
    const float2 a = __half22float2(*(const __half2*)&r.x);
    const float2 b = __half22float2(*(const __half2*)&r.y);
    acc.x = fmaf(w, a.x, acc.x); acc.y = fmaf(w, a.y, acc.y);
    acc.z = fmaf(w, b.x, acc.z); acc.w = fmaf(w, b.y, acc.w);
    sumw += w;
}

__global__ void __launch_bounds__(256) k_aggregate(float* __restrict__ out,
                                                   const float* __restrict__ bias) {
    const int n = (blockIdx.x * blockDim.x + threadIdx.x) >> 5;
    if (n >= N_NODES) return;
    const int lane = threadIdx.x & 31;
    const int head = lane >> 3;
    const int c0 = lane * 4;

    const int beg = __ldg(g_off + n);
    const int end = __ldg(g_off + n + 1);

    const float sd = __ldg(g_sdst + (size_t)n * 4 + head);
    const float bnd = leaky(fdec(g_maxss[head]) + sd);

    float4 acc = make_float4(0.f, 0.f, 0.f, 0.f);
    float sumw = 0.f;

    int p = beg;
    for (; p + 4 <= end; p += 4) {
        const int s0 = __ldg(g_csr_src + p);
        const int s1 = __ldg(g_csr_src + p + 1);
        const int s2 = __ldg(g_csr_src + p + 2);
        const int s3 = __ldg(g_csr_src + p + 3);
        edge_fma(s0, sd, bnd, head, c0, acc, sumw);
        edge_fma(s1, sd, bnd, head, c0, acc, sumw);
        edge_fma(s2, sd, bnd, head, c0, acc, sumw);
        edge_fma(s3, sd, bnd, head, c0, acc, sumw);
    }
    for (; p < end; p++) {
        const int s0 = __ldg(g_csr_src + p);
        edge_fma(s0, sd, bnd, head, c0, acc, sumw);
    }

    const float r = 1.f / (sumw + 1e-16f);
    const float4 b4 = __ldg((const float4*)(bias + c0));
    float4 o;
    o.x = fmaf(acc.x, r, b4.x);
    o.y = fmaf(acc.y, r, b4.y);
    o.z = fmaf(acc.z, r, b4.z);
    o.w = fmaf(acc.w, r, b4.w);
    *(float4*)(out + (size_t)n * OC + c0) = o;
}

// ---------------- launch ----------------
extern "C" void kernel_launch(void* const* d_in, const int* in_sizes, int n_in,
                              void* d_out, int out_size) {
    const float* x    = (const float*)d_in[0];
    const void*  ei   = d_in[1];
    const float* W    = (const float*)d_in[2];
    const float* att  = (const float*)d_in[3];
    const float* bias = (const float*)d_in[4];
    float*       out  = (float*)d_out;

    (void)in_sizes; (void)n_in; (void)out_size;

    k_init<<<(N_NODES + 255) / 256, 256>>>((const unsigned*)ei);
    k_gemm_mma<<<GEMM_CTAS, 256>>>(x, W, att, ei);
    k_scan_local<<<N_SCAN_BLOCKS, SCAN_BLK>>>();
    k_scan_bsum<<<1, 128>>>();
    k_scan_final<<<N_SCAN_BLOCKS, SCAN_BLK>>>();
    k_edge2<<<(E_EDGES / 2 + 255) / 256, 256>>>(ei);
    k_aggregate<<<(N_NODES * 32 + 255) / 256, 256>>>(out, bias);
}

// round 11
// speedup vs baseline: 1.1054x; 1.1054x over previous
#include <cuda_runtime.h>
#include <cuda_fp16.h>
#include <cstdint>

#define N_NODES 100000
#define E_EDGES 1600000
#define IN_CH   128
#define HEADS   4
#define OUT_CH  32
#define OC      (HEADS * OUT_CH)   // 128
#define NEG_SLOPE 0.2f

#define SCAN_BLK 1024
#define N_SCAN_BLOCKS ((N_NODES + SCAN_BLK - 1) / SCAN_BLK)   // 98
#define GEMM_CTAS ((N_NODES + 127) / 128)                     // 782

// ---------------- scratch (device globals; no allocation allowed) ----------
__device__ __align__(16) __half g_hh[(size_t)GEMM_CTAS * 128 * OC]; // fp16 h (padded)
__device__ __align__(16) float  g_ssrc[N_NODES * HEADS];
__device__ __align__(16) float  g_sdst[N_NODES * HEADS];
__device__ int g_csr_src[E_EDGES];
__device__ int g_rank[E_EDGES];
__device__ int g_deg[N_NODES];
__device__ int g_off[N_NODES + 1];
__device__ int g_bsum[N_SCAN_BLOCKS];
__device__ int g_bpre[N_SCAN_BLOCKS];
__device__ unsigned g_maxss[HEADS];
__device__ int g_is64;

__device__ __forceinline__ unsigned fenc(float f) {
    unsigned u = __float_as_uint(f);
    return (u & 0x80000000u) ? ~u : (u | 0x80000000u);
}
__device__ __forceinline__ float fdec(unsigned u) {
    return (u & 0x80000000u) ? __uint_as_float(u ^ 0x80000000u)
                             : __uint_as_float(~u);
}
__device__ __forceinline__ float leaky(float v) {
    return (v >= 0.f) ? v : NEG_SLOPE * v;
}

__device__ __forceinline__ void mma16816(float& d0, float& d1, float& d2, float& d3,
                                         unsigned a0, unsigned a1, unsigned a2, unsigned a3,
                                         unsigned b0, unsigned b1) {
    asm volatile("mma.sync.aligned.m16n8k16.row.col.f32.f16.f16.f32 "
                 "{%0,%1,%2,%3}, {%4,%5,%6,%7}, {%8,%9}, {%0,%1,%2,%3};"
                 : "+f"(d0), "+f"(d1), "+f"(d2), "+f"(d3)
                 : "r"(a0), "r"(a1), "r"(a2), "r"(a3), "r"(b0), "r"(b1));
}

// ---------------- K0: init + parallel dtype detect ---------------------------
__global__ void k_init(const unsigned* __restrict__ ei32) {
    const int i = blockIdx.x * blockDim.x + threadIdx.x;
    if (i < N_NODES) g_deg[i] = 0;
    if (i < HEADS) g_maxss[i] = fenc(-__int_as_float(0x7f800000));
    if (blockIdx.x == 0 && threadIdx.x < 64) {
        const unsigned w = ei32[2 * threadIdx.x + 1];
        const unsigned nz = __ballot_sync(0xffffffffu, w != 0u);
        __shared__ int anynz;
        if (threadIdx.x == 0) anynz = 0;
        __syncthreads();
        if (nz) atomicOr(&anynz, 1);
        __syncthreads();
        if (threadIdx.x == 0) g_is64 = anynz ? 0 : 1;
    }
}

// ---------------- K1: tensor-core GEMM + fused scores -----------------------
#define APAD 72   // 64 + 8 halves pad
__global__ void __launch_bounds__(256) k_gemm_mma(const float* __restrict__ x,
                                                  const float* __restrict__ W,
                                                  const float* __restrict__ att) {
    __shared__ __half As[128][APAD];
    __shared__ __half Bs[128][APAD];

    const int nbase = blockIdx.x * 128;
    const int t = threadIdx.x;
    const int wid = t >> 5;
    const int lane = t & 31;
    const int g = lane >> 2;
    const int tid = lane & 3;

    float d[16][4];
    #pragma unroll
    for (int nt = 0; nt < 16; nt++)
        #pragma unroll
        for (int q = 0; q < 4; q++) d[nt][q] = 0.f;

    #pragma unroll
    for (int kp = 0; kp < 2; kp++) {
        #pragma unroll
        for (int i = 0; i < 8; i++) {
            const int id = t + i * 256;
            const int row = id >> 4;
            const int c4 = (id & 15) * 4;
            const int node = nbase + row;
            float4 v = make_float4(0.f, 0.f, 0.f, 0.f);
            if (node < N_NODES)
                v = __ldg((const float4*)(x + (size_t)node * IN_CH + kp * 64 + c4));
            __half h4[4] = {__float2half_rn(v.x), __float2half_rn(v.y),
                            __float2half_rn(v.z), __float2half_rn(v.w)};
            *(uint2*)&As[row][c4] = *(uint2*)h4;
        }
        #pragma unroll
        for (int i = 0; i < 8; i++) {
            const int id = t + i * 256;
            const int k = id >> 5;
            const int n4 = (id & 31) * 4;
            const float4 w4 = __ldg((const float4*)(W + (size_t)(kp * 64 + k) * OC + n4));
            Bs[n4 + 0][k] = __float2half_rn(w4.x);
            Bs[n4 + 1][k] = __float2half_rn(w4.y);
            Bs[n4 + 2][k] = __float2half_rn(w4.z);
            Bs[n4 + 3][k] = __float2half_rn(w4.w);
        }
        __syncthreads();

        const int r0 = wid * 16 + g;
        #pragma unroll
        for (int ks = 0; ks < 4; ks++) {
            const int kk = ks * 16 + tid * 2;
            const unsigned a0 = *(const unsigned*)&As[r0][kk];
            const unsigned a1 = *(const unsigned*)&As[r0 + 8][kk];
            const unsigned a2 = *(const unsigned*)&As[r0][kk + 8];
            const unsigned a3 = *(const unsigned*)&As[r0 + 8][kk + 8];
            #pragma unroll
            for (int nt = 0; nt < 16; nt++) {
                const int n = nt * 8 + g;
                const unsigned b0 = *(const unsigned*)&Bs[n][kk];
                const unsigned b1 = *(const unsigned*)&Bs[n][kk + 8];
                mma16816(d[nt][0], d[nt][1], d[nt][2], d[nt][3],
                         a0, a1, a2, a3, b0, b1);
            }
        }
        __syncthreads();
    }

    // ---- epilogue: store h (fp16) + fused scores ----
    const int node0 = nbase + wid * 16 + g;
    const int node1 = node0 + 8;

    #pragma unroll
    for (int nt = 0; nt < 16; nt++) {
        const int col = nt * 8 + tid * 2;
        const __half2 h01 = __floats2half2_rn(d[nt][0], d[nt][1]);
        const __half2 h23 = __floats2half2_rn(d[nt][2], d[nt][3]);
        *(__half2*)(g_hh + (size_t)node0 * OC + col) = h01;
        *(__half2*)(g_hh + (size_t)node1 * OC + col) = h23;
    }

    float ssA[4] = {0,0,0,0}, sdA[4] = {0,0,0,0};
    float ssB[4] = {0,0,0,0}, sdB[4] = {0,0,0,0};
    #pragma unroll
    for (int h = 0; h < 4; h++) {
        #pragma unroll
        for (int j = 0; j < 4; j++) {
            const int nt = h * 4 + j;
            const int off = j * 8 + tid * 2;
            const float2 as2 = __ldg((const float2*)(att + h * 64 + off));
            const float2 ad2 = __ldg((const float2*)(att + h * 64 + 32 + off));
            ssA[h] += d[nt][0] * as2.x + d[nt][1] * as2.y;
            sdA[h] += d[nt][0] * ad2.x + d[nt][1] * ad2.y;
            ssB[h] += d[nt][2] * as2.x + d[nt][3] * as2.y;
            sdB[h] += d[nt][2] * ad2.x + d[nt][3] * ad2.y;
        }
    }
    #pragma unroll
    for (int h = 0; h < 4; h++) {
        #pragma unroll
        for (int off = 1; off <= 2; off <<= 1) {
            ssA[h] += __shfl_xor_sync(0xffffffffu, ssA[h], off);
            sdA[h] += __shfl_xor_sync(0xffffffffu, sdA[h], off);
            ssB[h] += __shfl_xor_sync(0xffffffffu, ssB[h], off);
            sdB[h] += __shfl_xor_sync(0xffffffffu, sdB[h], off);
        }
    }
    if (tid == 0) {
        if (node0 < N_NODES) {
            *(float4*)(g_ssrc + (size_t)node0 * 4) = make_float4(ssA[0], ssA[1], ssA[2], ssA[3]);
            *(float4*)(g_sdst + (size_t)node0 * 4) = make_float4(sdA[0], sdA[1], sdA[2], sdA[3]);
        }
        if (node1 < N_NODES) {
            *(float4*)(g_ssrc + (size_t)node1 * 4) = make_float4(ssB[0], ssB[1], ssB[2], ssB[3]);
            *(float4*)(g_sdst + (size_t)node1 * 4) = make_float4(sdB[0], sdB[1], sdB[2], sdB[3]);
        }
    }
    const float NINF = -__int_as_float(0x7f800000);
    float mm[4];
    #pragma unroll
    for (int h = 0; h < 4; h++) {
        float a = (node0 < N_NODES) ? ssA[h] : NINF;
        float b = (node1 < N_NODES) ? ssB[h] : NINF;
        mm[h] = fmaxf(a, b);
        #pragma unroll
        for (int off = 4; off <= 16; off <<= 1)
            mm[h] = fmaxf(mm[h], __shfl_xor_sync(0xffffffffu, mm[h], off));
    }
    if (lane < 4)
        atomicMax(&g_maxss[lane], fenc(mm[lane]));
}

// ---------------- K2: degree histogram + per-edge rank ----------------------
__global__ void k_hist(const void* __restrict__ ei) {
    const int e = blockIdx.x * blockDim.x + threadIdx.x;
    if (e >= E_EDGES) return;
    int dst;
    if (g_is64) dst = (int)((const long long*)ei)[E_EDGES + e];
    else        dst = ((const int*)ei)[E_EDGES + e];
    g_rank[e] = atomicAdd(&g_deg[dst], 1);   // rank within dst segment
}

// ---------------- K3a/b/c: device-wide exclusive scan ------------------------
__global__ void __launch_bounds__(SCAN_BLK) k_scan_local() {
    __shared__ int ws[32];
    const int t = threadIdx.x;
    const int lane = t & 31;
    const int warp = t >> 5;
    const int i = blockIdx.x * SCAN_BLK + t;

    const int val = (i < N_NODES) ? g_deg[i] : 0;
    int v = val;
    #pragma unroll
    for (int d = 1; d < 32; d <<= 1) {
        const int u = __shfl_up_sync(0xffffffffu, v, d);
        if (lane >= d) v += u;
    }
    if (lane == 31) ws[warp] = v;
    __syncthreads();
    if (warp == 0) {
        int w = ws[lane];
        #pragma unroll
        for (int d = 1; d < 32; d <<= 1) {
            const int u = __shfl_up_sync(0xffffffffu, w, d);
            if (lane >= d) w += u;
        }
        ws[lane] = w;
    }
    __syncthreads();
    const int incl = v + (warp ? ws[warp - 1] : 0);
    if (i < N_NODES) g_off[i] = incl - val;
    if (t == SCAN_BLK - 1) g_bsum[blockIdx.x] = incl;
}

__global__ void __launch_bounds__(128) k_scan_bsum() {
    __shared__ int ws[4];
    const int t = threadIdx.x;
    const int lane = t & 31;
    const int warp = t >> 5;
    const int val = (t < N_SCAN_BLOCKS) ? g_bsum[t] : 0;
    int v = val;
    #pragma unroll
    for (int d = 1; d < 32; d <<= 1) {
        const int u = __shfl_up_sync(0xffffffffu, v, d);
        if (lane >= d) v += u;
    }
    if (lane == 31) ws[warp] = v;
    __syncthreads();
    int wpre = 0;
    #pragma unroll
    for (int w = 0; w < 4; w++) if (w < warp) wpre += ws[w];
    if (t < N_SCAN_BLOCKS) g_bpre[t] = v - val + wpre;
}

__global__ void __launch_bounds__(SCAN_BLK) k_scan_final() {
    const int i = blockIdx.x * SCAN_BLK + threadIdx.x;
    if (i < N_NODES)
        g_off[i] += g_bpre[blockIdx.x];
    if (i == 0) g_off[N_NODES] = E_EDGES;
}

// ---------------- K4: CSR scatter (no atomics: off[dst] + rank) -------------
__global__ void k_edge2(const void* __restrict__ ei) {
    const int e = blockIdx.x * blockDim.x + threadIdx.x;
    if (e >= E_EDGES) return;
    int src, dst;
    if (g_is64) {
        const long long* p = (const long long*)ei;
        src = (int)p[e]; dst = (int)p[E_EDGES + e];
    } else {
        const int* p = (const int*)ei;
        src = p[e]; dst = p[E_EDGES + e];
    }
    const int pos = __ldg(g_off + dst) + g_rank[e];
    g_csr_src[pos] = src;
}

// ---------------- K5: aggregation w/ on-the-fly softmax (1 warp/node) ------
__device__ __forceinline__ void edge_fma(int src, float sd, float bnd, int head, int c0,
                                         float4& acc, float& sumw) {
    const float ss = __ldg(g_ssrc + (size_t)src * 4 + head);
    const float w = __expf(leaky(ss + sd) - bnd);
    const uint2 r = *(const uint2*)(g_hh + (size_t)src * OC + c0);
    const float2 a = __half22float2(*(const __half2*)&r.x);
    const float2 b = __half22float2(*(const __half2*)&r.y);
    acc.x = fmaf(w, a.x, acc.x); acc.y = fmaf(w, a.y, acc.y);
    acc.z = fmaf(w, b.x, acc.z); acc.w = fmaf(w, b.y, acc.w);
    sumw += w;
}

__global__ void __launch_bounds__(256) k_aggregate(float* __restrict__ out,
                                                   const float* __restrict__ bias) {
    const int n = (blockIdx.x * blockDim.x + threadIdx.x) >> 5;
    if (n >= N_NODES) return;
    const int lane = threadIdx.x & 31;
    const int head = lane >> 3;
    const int c0 = lane * 4;

    const int beg = __ldg(g_off + n);
    const int end = __ldg(g_off + n + 1);

    const float sd = __ldg(g_sdst + (size_t)n * 4 + head);
    const float bnd = leaky(fdec(g_maxss[head]) + sd);

    float4 acc = make_float4(0.f, 0.f, 0.f, 0.f);
    float sumw = 0.f;

    int p = beg;
    for (; p + 4 <= end; p += 4) {
        const int s0 = __ldg(g_csr_src + p);
        const int s1 = __ldg(g_csr_src + p + 1);
        const int s2 = __ldg(g_csr_src + p + 2);
        const int s3 = __ldg(g_csr_src + p + 3);
        edge_fma(s0, sd, bnd, head, c0, acc, sumw);
        edge_fma(s1, sd, bnd, head, c0, acc, sumw);
        edge_fma(s2, sd, bnd, head, c0, acc, sumw);
        edge_fma(s3, sd, bnd, head, c0, acc, sumw);
    }
    for (; p < end; p++) {
        const int s0 = __ldg(g_csr_src + p);
        edge_fma(s0, sd, bnd, head, c0, acc, sumw);
    }

    const float r = 1.f / (sumw + 1e-16f);
    const float4 b4 = __ldg((const float4*)(bias + c0));
    float4 o;
    o.x = fmaf(acc.x, r, b4.x);
    o.y = fmaf(acc.y, r, b4.y);
    o.z = fmaf(acc.z, r, b4.z);
    o.w = fmaf(acc.w, r, b4.w);
    *(float4*)(out + (size_t)n * OC + c0) = o;
}

// ---------------- launch ----------------
extern "C" void kernel_launch(void* const* d_in, const int* in_sizes, int n_in,
                              void* d_out, int out_size) {
    const float* x    = (const float*)d_in[0];
    const void*  ei   = d_in[1];
    const float* W    = (const float*)d_in[2];
    const float* att  = (const float*)d_in[3];
    const float* bias = (const float*)d_in[4];
    float*       out  = (float*)d_out;

    (void)in_sizes; (void)n_in; (void)out_size;

    k_init<<<(N_NODES + 255) / 256, 256>>>((const unsigned*)ei);
    k_gemm_mma<<<GEMM_CTAS, 256>>>(x, W, att);
    k_hist<<<(E_EDGES + 255) / 256, 256>>>(ei);
    k_scan_local<<<N_SCAN_BLOCKS, SCAN_BLK>>>();
    k_scan_bsum<<<1, 128>>>();
    k_scan_final<<<N_SCAN_BLOCKS, SCAN_BLK>>>();
    k_edge2<<<(E_EDGES + 255) / 256, 256>>>(ei);
    k_aggregate<<<(N_NODES * 32 + 255) / 256, 256>>>(out, bias);
}